// round 8
// baseline (speedup 1.0000x reference)
#include <cuda_runtime.h>
#include <cstdint>

#define B 8
#define O 2048
#define Q 2048
#define D 128
#define KT 13      // expansion terms k = 0..12
#define NCH 64     // obs chunks per batch
#define CH 32      // obs rows per chunk

// Scratch (allocation-free rule: device globals)
__device__ __align__(16) float g_Mpart[B * NCH * KT * D];  // per-chunk moment partials
__device__ __align__(16) float g_mspart[B * NCH * KT];     // per-chunk weight-sum partials
__device__ __align__(16) float g_Mp[B * KT * D];           // projected moments
__device__ __align__(16) float g_msum[B * KT];             // weight-sum moments

__constant__ float c_invk[KT] = {0.f, 1.f, 1.f/2, 1.f/3, 1.f/4, 1.f/5, 1.f/6,
                                 1.f/7, 1.f/8, 1.f/9, 1.f/10, 1.f/11, 1.f/12};

// ---------------------------------------------------------------------------
// Kernel A: per (batch, 32-obs chunk) moment partials.
//   g_k(o) = mask_o * exp(-0.5*c2*t_o^2) * (c2*t_o)^k / k!
//   Mpart[k][e] = sum_o g_k(o)*emb[o][e] ;  mspart[k] = sum_o g_k(o)
// 512 CTAs x 512 threads (16 warps -> ~55 warps/SM resident).
// Thread: e = tid&127, quarter = tid>>7 owns 8 rows, loads front-batched.
// ---------------------------------------------------------------------------
__global__ __launch_bounds__(512) void k_moments(
    const float* __restrict__ obs_emb,
    const float* __restrict__ obs_times,
    const float* __restrict__ obs_mask,
    const float* __restrict__ log_sigma)
{
    __shared__ __align__(16) float g_s[CH * 16];        // 13 used, padded to 16
    __shared__ __align__(16) float red[3 * KT * D];     // quarters 1..3

    const int tid = threadIdx.x;
    const int c   = blockIdx.x;
    const int b   = blockIdx.y;
    const int o0  = c * CH;

    const int e  = tid & 127;
    const int qa = tid >> 7;            // 0..3, 8 rows each

    // ---- front-batched emb loads (independent of g_s) ----
    const float* ebase = obs_emb + ((size_t)(b * O) + o0 + qa * 8) * D + e;
    float x[8];
#pragma unroll
    for (int oo = 0; oo < 8; ++oo) x[oo] = __ldg(ebase + (size_t)oo * D);

    const float c2 = __expf(-2.0f * log_sigma[0]);   // 1/sigma^2

    // Phase 1: 32 threads compute g_k rows (overlaps with loads above)
    if (tid < CH) {
        const int o = o0 + tid;
        const float t  = obs_times[b * O + o];
        const float mk = obs_mask[b * O + o];
        const float xx = c2 * t;
        float g = mk * __expf(-0.5f * c2 * t * t);
        g_s[tid * 16 + 0] = g;
#pragma unroll
        for (int k = 1; k < KT; ++k) {
            g *= xx * c_invk[k];
            g_s[tid * 16 + k] = g;
        }
    }
    __syncthreads();

    // ms partials (tiny)
    if (tid < KT) {
        float s = 0.0f;
#pragma unroll
        for (int o = 0; o < CH; ++o) s += g_s[o * 16 + tid];
        g_mspart[(b * NCH + c) * KT + tid] = s;
    }

    // Phase 2: accumulate moments over 8 rows per thread.
    float acc[KT];
#pragma unroll
    for (int k = 0; k < KT; ++k) acc[k] = 0.0f;

    const float* gbase = g_s + qa * 8 * 16;
#pragma unroll
    for (int oo = 0; oo < 8; ++oo) {
        const float xv = x[oo];
        const float4 ga = *(const float4*)(gbase + oo * 16 + 0);
        const float4 gb = *(const float4*)(gbase + oo * 16 + 4);
        const float4 gc = *(const float4*)(gbase + oo * 16 + 8);
        const float  gd = gbase[oo * 16 + 12];
        acc[0] = fmaf(ga.x, xv, acc[0]);   acc[1] = fmaf(ga.y, xv, acc[1]);
        acc[2] = fmaf(ga.z, xv, acc[2]);   acc[3] = fmaf(ga.w, xv, acc[3]);
        acc[4] = fmaf(gb.x, xv, acc[4]);   acc[5] = fmaf(gb.y, xv, acc[5]);
        acc[6] = fmaf(gb.z, xv, acc[6]);   acc[7] = fmaf(gb.w, xv, acc[7]);
        acc[8] = fmaf(gc.x, xv, acc[8]);   acc[9] = fmaf(gc.y, xv, acc[9]);
        acc[10] = fmaf(gc.z, xv, acc[10]); acc[11] = fmaf(gc.w, xv, acc[11]);
        acc[12] = fmaf(gd, xv, acc[12]);
    }

    // combine the four quarters via SMEM (quarters 1..3 store, quarter 0 sums)
    if (qa > 0) {
        float* dst = red + (qa - 1) * KT * D + e;
#pragma unroll
        for (int k = 0; k < KT; ++k) dst[k * D] = acc[k];
    }
    __syncthreads();
    if (qa == 0) {
        float* dst = g_Mpart + (size_t)((b * NCH + c) * KT) * D + e;
        const float* r0 = red + e;
#pragma unroll
        for (int k = 0; k < KT; ++k)
            dst[k * D] = acc[k] + r0[k * D] + r0[KT * D + k * D] + r0[2 * KT * D + k * D];
    }
}

// ---------------------------------------------------------------------------
// Kernel B: reduce chunk partials and project through W.
// One CTA per (b, k), 512 threads: c-sum split 4-way (16 chunks each, MLP 16).
// ---------------------------------------------------------------------------
__global__ __launch_bounds__(512) void k_reduce_project(
    const float* __restrict__ W_proj)
{
    __shared__ __align__(16) float m_s[D];
    __shared__ __align__(16) float red[3 * D];
    __shared__ float msred[2];
    const int tid = threadIdx.x;
    const int e   = tid & 127;
    const int h   = tid >> 7;          // 0..3
    const int k = blockIdx.x % KT;
    const int b = blockIdx.x / KT;

    const float* src = g_Mpart + (size_t)((b * NCH + h * 16) * KT + k) * D + e;
    float p[16];
#pragma unroll
    for (int c = 0; c < 16; ++c) p[c] = __ldg(src + (size_t)c * KT * D);
    float s = 0.0f;
#pragma unroll
    for (int c = 0; c < 16; ++c) s += p[c];
    if (h > 0) red[(h - 1) * D + e] = s;

    // msum: 64 threads, one chunk each, warp-reduce
    if (tid < 64) {
        float ms = g_mspart[(b * NCH + tid) * KT + k];
#pragma unroll
        for (int off = 16; off > 0; off >>= 1)
            ms += __shfl_down_sync(0xffffffffu, ms, off);
        if ((tid & 31) == 0) msred[tid >> 5] = ms;
    }
    __syncthreads();
    if (tid == 0) g_msum[b * KT + k] = msred[0] + msred[1];
    if (h == 0) m_s[e] = s + red[e] + red[D + e] + red[2 * D + e];
    __syncthreads();

    if (h == 0) {
        // thread e = output dim: dot(W[e][:], m)
        const float4* wrow = (const float4*)(W_proj + (size_t)e * D);
        float dot = 0.0f;
#pragma unroll
        for (int i = 0; i < D / 4; ++i) {
            float4 w4 = wrow[i];
            const float4 m4 = *(const float4*)&m_s[i * 4];
            dot += w4.x * m4.x + w4.y * m4.y + w4.z * m4.z + w4.w * m4.w;
        }
        g_Mp[(size_t)(b * KT + k) * D + e] = dot;
    }
}

// ---------------------------------------------------------------------------
// Kernel C: combine. out[q][e'] = (sum_k f_k(q) Mp[k][e']) / (sum_k f_k msum[k]) + b[e']
// float4 variant: thread owns 4 e-cols, qh = tid>>5 handles 2 q's.
// Mp/msum in registers. 1024 CTAs (16 q each), 256 threads.
// ---------------------------------------------------------------------------
__global__ __launch_bounds__(256) void k_combine(
    const float* __restrict__ query_times,
    const float* __restrict__ log_sigma,
    const float* __restrict__ b_proj,
    float* __restrict__ out)
{
    const int tid = threadIdx.x;
    const int b   = blockIdx.y;
    const int q0  = blockIdx.x * 16;
    const int e   = (tid & 31) * 4;
    const int qh  = tid >> 5;          // 0..7, 2 q's each

    const float* qtp = query_times + b * Q + q0 + qh * 2;
    const float qt0 = qtp[0];
    const float qt1 = qtp[1];

    float4 mp[KT];
    float  ms[KT];
    const float* mpb = g_Mp + (size_t)b * KT * D + e;
    const float* msb = g_msum + b * KT;
#pragma unroll
    for (int k = 0; k < KT; ++k) {
        mp[k] = *(const float4*)(mpb + k * D);
        ms[k] = msb[k];
    }

    const float c2 = __expf(-2.0f * log_sigma[0]);
    const float4 bp = *(const float4*)&b_proj[e];
    float* ob = out + ((size_t)(b * Q) + q0 + qh * 2) * D + e;

#pragma unroll
    for (int i = 0; i < 2; ++i) {
        const float qt = (i == 0) ? qt0 : qt1;
        float f = __expf(-0.5f * c2 * qt * qt);
        float4 num;
        num.x = f * mp[0].x; num.y = f * mp[0].y;
        num.z = f * mp[0].z; num.w = f * mp[0].w;
        float den = f * ms[0];
#pragma unroll
        for (int k = 1; k < KT; ++k) {
            f *= qt;
            num.x = fmaf(f, mp[k].x, num.x);
            num.y = fmaf(f, mp[k].y, num.y);
            num.z = fmaf(f, mp[k].z, num.z);
            num.w = fmaf(f, mp[k].w, num.w);
            den = fmaf(f, ms[k], den);
        }
        const float inv = __fdividef(1.0f, fmaxf(den, 1e-8f));
        float4 v;
        v.x = fmaf(num.x, inv, bp.x);
        v.y = fmaf(num.y, inv, bp.y);
        v.z = fmaf(num.z, inv, bp.z);
        v.w = fmaf(num.w, inv, bp.w);
        *(float4*)(ob + (size_t)i * D) = v;
    }
}

// ---------------------------------------------------------------------------
extern "C" void kernel_launch(void* const* d_in, const int* in_sizes, int n_in,
                              void* d_out, int out_size) {
    const float* obs_emb     = (const float*)d_in[0];
    const float* obs_times   = (const float*)d_in[1];
    const float* query_times = (const float*)d_in[2];
    const float* obs_mask    = (const float*)d_in[3];
    const float* log_sigma   = (const float*)d_in[4];
    const float* W_proj      = (const float*)d_in[5];
    const float* b_proj      = (const float*)d_in[6];
    float* out = (float*)d_out;

    dim3 gA(NCH, B);
    k_moments<<<gA, 512>>>(obs_emb, obs_times, obs_mask, log_sigma);
    k_reduce_project<<<B * KT, 512>>>(W_proj);
    dim3 gC(Q / 16, B);
    k_combine<<<gC, 256>>>(query_times, log_sigma, b_proj, out);
}

// round 9
// speedup vs baseline: 1.0553x; 1.0553x over previous
#include <cuda_runtime.h>
#include <cstdint>

#define B 8
#define O 2048
#define Q 2048
#define D 128
#define KT 13      // expansion terms k = 0..12
#define NCH 64     // obs chunks per batch
#define CH 32      // obs rows per chunk

// Scratch (allocation-free rule: device globals; zero-initialized at load).
// g_M / g_msum_in are atomic accumulators; kernel B consumes AND re-zeros
// them each call, so every kernel_launch invocation starts from zeros.
__device__ float g_M[B * KT * D];        // accumulated moments
__device__ float g_msum_in[B * KT];      // accumulated weight sums
__device__ __align__(16) float g_Mp[B * KT * D];   // projected moments
__device__ __align__(16) float g_msum[B * KT];     // weight-sum moments (for C)

__constant__ float c_invk[KT] = {0.f, 1.f, 1.f/2, 1.f/3, 1.f/4, 1.f/5, 1.f/6,
                                 1.f/7, 1.f/8, 1.f/9, 1.f/10, 1.f/11, 1.f/12};

// ---------------------------------------------------------------------------
// Kernel A: per (batch, 32-obs chunk) moments, reduced across CTAs via RED.
//   g_k(o) = mask_o * exp(-0.5*c2*t_o^2) * (c2*t_o)^k / k!
//   g_M[b][k][e] += sum_o g_k(o)*emb[o][e] ;  g_msum_in[b][k] += sum_o g_k(o)
// 512 CTAs x 512 threads. Thread: e = tid&127, quarter = tid>>7 owns 8 rows.
// ---------------------------------------------------------------------------
__global__ __launch_bounds__(512) void k_moments(
    const float* __restrict__ obs_emb,
    const float* __restrict__ obs_times,
    const float* __restrict__ obs_mask,
    const float* __restrict__ log_sigma)
{
    __shared__ __align__(16) float g_s[CH * 16];        // 13 used, padded to 16
    __shared__ __align__(16) float red[3 * KT * D];     // quarters 1..3

    const int tid = threadIdx.x;
    const int c   = blockIdx.x;
    const int b   = blockIdx.y;
    const int o0  = c * CH;

    const int e  = tid & 127;
    const int qa = tid >> 7;            // 0..3, 8 rows each

    // ---- front-batched emb loads (independent of g_s) ----
    const float* ebase = obs_emb + ((size_t)(b * O) + o0 + qa * 8) * D + e;
    float x[8];
#pragma unroll
    for (int oo = 0; oo < 8; ++oo) x[oo] = __ldg(ebase + (size_t)oo * D);

    const float c2 = __expf(-2.0f * log_sigma[0]);   // 1/sigma^2

    // Phase 1: 32 threads compute g_k rows (overlaps with loads above)
    if (tid < CH) {
        const int o = o0 + tid;
        const float t  = obs_times[b * O + o];
        const float mk = obs_mask[b * O + o];
        const float xx = c2 * t;
        float g = mk * __expf(-0.5f * c2 * t * t);
        g_s[tid * 16 + 0] = g;
#pragma unroll
        for (int k = 1; k < KT; ++k) {
            g *= xx * c_invk[k];
            g_s[tid * 16 + k] = g;
        }
    }
    __syncthreads();

    // ms partials -> atomic accumulate
    if (tid < KT) {
        float s = 0.0f;
#pragma unroll
        for (int o = 0; o < CH; ++o) s += g_s[o * 16 + tid];
        atomicAdd(&g_msum_in[b * KT + tid], s);
    }

    // Phase 2: accumulate moments over 8 rows per thread.
    float acc[KT];
#pragma unroll
    for (int k = 0; k < KT; ++k) acc[k] = 0.0f;

    const float* gbase = g_s + qa * 8 * 16;
#pragma unroll
    for (int oo = 0; oo < 8; ++oo) {
        const float xv = x[oo];
        const float4 ga = *(const float4*)(gbase + oo * 16 + 0);
        const float4 gb = *(const float4*)(gbase + oo * 16 + 4);
        const float4 gc = *(const float4*)(gbase + oo * 16 + 8);
        const float  gd = gbase[oo * 16 + 12];
        acc[0] = fmaf(ga.x, xv, acc[0]);   acc[1] = fmaf(ga.y, xv, acc[1]);
        acc[2] = fmaf(ga.z, xv, acc[2]);   acc[3] = fmaf(ga.w, xv, acc[3]);
        acc[4] = fmaf(gb.x, xv, acc[4]);   acc[5] = fmaf(gb.y, xv, acc[5]);
        acc[6] = fmaf(gb.z, xv, acc[6]);   acc[7] = fmaf(gb.w, xv, acc[7]);
        acc[8] = fmaf(gc.x, xv, acc[8]);   acc[9] = fmaf(gc.y, xv, acc[9]);
        acc[10] = fmaf(gc.z, xv, acc[10]); acc[11] = fmaf(gc.w, xv, acc[11]);
        acc[12] = fmaf(gd, xv, acc[12]);
    }

    // combine the four quarters via SMEM (quarters 1..3 store, quarter 0 REDs)
    if (qa > 0) {
        float* dst = red + (qa - 1) * KT * D + e;
#pragma unroll
        for (int k = 0; k < KT; ++k) dst[k * D] = acc[k];
    }
    __syncthreads();
    if (qa == 0) {
        float* dst = g_M + (size_t)(b * KT) * D + e;
        const float* r0 = red + e;
#pragma unroll
        for (int k = 0; k < KT; ++k) {
            const float v = acc[k] + r0[k * D] + r0[KT * D + k * D]
                          + r0[2 * KT * D + k * D];
            atomicAdd(dst + k * D, v);      // RED.ADD, coalesced across e
        }
    }
}

// ---------------------------------------------------------------------------
// Kernel B: project accumulated moments through W; consume-and-rezero the
// atomic buffers so the next kernel_launch call starts from zeros.
//   Mp[b][k][e'] = sum_e W[e'][e] * g_M[b][k][e]
// One CTA per (b, k), 128 threads.
// ---------------------------------------------------------------------------
__global__ __launch_bounds__(128) void k_project(
    const float* __restrict__ W_proj)
{
    __shared__ __align__(16) float m_s[D];
    const int e = threadIdx.x;
    const int k = blockIdx.x % KT;
    const int b = blockIdx.x / KT;

    float* mcell = g_M + (size_t)(b * KT + k) * D + e;
    m_s[e] = *mcell;
    *mcell = 0.0f;                       // restore zero state
    if (e == 0) {
        g_msum[b * KT + k] = g_msum_in[b * KT + k];
        g_msum_in[b * KT + k] = 0.0f;    // restore zero state
    }
    __syncthreads();

    // thread e = output dim: dot(W[e][:], m)
    const float4* wrow = (const float4*)(W_proj + (size_t)e * D);
    float dot = 0.0f;
#pragma unroll
    for (int i = 0; i < D / 4; ++i) {
        float4 w4 = wrow[i];
        const float4 m4 = *(const float4*)&m_s[i * 4];
        dot += w4.x * m4.x + w4.y * m4.y + w4.z * m4.z + w4.w * m4.w;
    }
    g_Mp[(size_t)(b * KT + k) * D + e] = dot;
}

// ---------------------------------------------------------------------------
// Kernel C: combine. out[q][e'] = (sum_k f_k(q) Mp[k][e']) / (sum_k f_k msum[k]) + b[e']
// float4 variant: thread owns 4 e-cols, qh = tid>>5 handles 2 q's.
// Mp/msum in registers. 1024 CTAs (16 q each), 256 threads.
// ---------------------------------------------------------------------------
__global__ __launch_bounds__(256) void k_combine(
    const float* __restrict__ query_times,
    const float* __restrict__ log_sigma,
    const float* __restrict__ b_proj,
    float* __restrict__ out)
{
    const int tid = threadIdx.x;
    const int b   = blockIdx.y;
    const int q0  = blockIdx.x * 16;
    const int e   = (tid & 31) * 4;
    const int qh  = tid >> 5;          // 0..7, 2 q's each

    const float* qtp = query_times + b * Q + q0 + qh * 2;
    const float qt0 = qtp[0];
    const float qt1 = qtp[1];

    float4 mp[KT];
    float  ms[KT];
    const float* mpb = g_Mp + (size_t)b * KT * D + e;
    const float* msb = g_msum + b * KT;
#pragma unroll
    for (int k = 0; k < KT; ++k) {
        mp[k] = *(const float4*)(mpb + k * D);
        ms[k] = msb[k];
    }

    const float c2 = __expf(-2.0f * log_sigma[0]);
    const float4 bp = *(const float4*)&b_proj[e];
    float* ob = out + ((size_t)(b * Q) + q0 + qh * 2) * D + e;

#pragma unroll
    for (int i = 0; i < 2; ++i) {
        const float qt = (i == 0) ? qt0 : qt1;
        float f = __expf(-0.5f * c2 * qt * qt);
        float4 num;
        num.x = f * mp[0].x; num.y = f * mp[0].y;
        num.z = f * mp[0].z; num.w = f * mp[0].w;
        float den = f * ms[0];
#pragma unroll
        for (int k = 1; k < KT; ++k) {
            f *= qt;
            num.x = fmaf(f, mp[k].x, num.x);
            num.y = fmaf(f, mp[k].y, num.y);
            num.z = fmaf(f, mp[k].z, num.z);
            num.w = fmaf(f, mp[k].w, num.w);
            den = fmaf(f, ms[k], den);
        }
        const float inv = __fdividef(1.0f, fmaxf(den, 1e-8f));
        float4 v;
        v.x = fmaf(num.x, inv, bp.x);
        v.y = fmaf(num.y, inv, bp.y);
        v.z = fmaf(num.z, inv, bp.z);
        v.w = fmaf(num.w, inv, bp.w);
        *(float4*)(ob + (size_t)i * D) = v;
    }
}

// ---------------------------------------------------------------------------
extern "C" void kernel_launch(void* const* d_in, const int* in_sizes, int n_in,
                              void* d_out, int out_size) {
    const float* obs_emb     = (const float*)d_in[0];
    const float* obs_times   = (const float*)d_in[1];
    const float* query_times = (const float*)d_in[2];
    const float* obs_mask    = (const float*)d_in[3];
    const float* log_sigma   = (const float*)d_in[4];
    const float* W_proj      = (const float*)d_in[5];
    const float* b_proj      = (const float*)d_in[6];
    float* out = (float*)d_out;

    dim3 gA(NCH, B);
    k_moments<<<gA, 512>>>(obs_emb, obs_times, obs_mask, log_sigma);
    k_project<<<B * KT, 128>>>(W_proj);
    dim3 gC(Q / 16, B);
    k_combine<<<gC, 256>>>(query_times, log_sigma, b_proj, out);
}